// round 16
// baseline (speedup 1.0000x reference)
#include <cuda_runtime.h>
#include <cuda_fp16.h>
#include <math.h>
#include <stdint.h>

// Problem constants
#define Bsz  64
#define Nn   512
#define Mm   256
#define Dd   1024
#define ROWS (Bsz * Nn)        // 32768
#define POS  256               // 16x16 spatial positions

// ===========================================================================
// Low-level helpers
// ===========================================================================
__device__ __forceinline__ uint32_t smem_u32(const void* p) {
    uint32_t a;
    asm("{ .reg .u64 t; cvta.to.shared.u64 t, %1; cvt.u32.u64 %0, t; }"
        : "=r"(a) : "l"(p));
    return a;
}

__device__ __forceinline__ void cp16(void* sptr, const void* gptr) {
    uint32_t s = smem_u32(sptr);
    asm volatile("cp.async.cg.shared.global [%0], [%1], 16;" :: "r"(s), "l"(gptr));
}
#define CP_COMMIT() asm volatile("cp.async.commit_group;" ::: "memory")
#define CP_WAIT1()  asm volatile("cp.async.wait_group 1;" ::: "memory")

__device__ __forceinline__ void ldsm4(uint32_t& r0, uint32_t& r1, uint32_t& r2,
                                      uint32_t& r3, uint32_t addr) {
    asm volatile("ldmatrix.sync.aligned.m8n8.x4.shared.b16 {%0,%1,%2,%3}, [%4];"
                 : "=r"(r0), "=r"(r1), "=r"(r2), "=r"(r3) : "r"(addr));
}

// fp16 MMA, fp32 accumulate
__device__ __forceinline__ void mma16816(float* c, const uint32_t* a,
                                         uint32_t b0, uint32_t b1) {
    asm volatile(
        "mma.sync.aligned.m16n8k16.row.col.f32.f16.f16.f32 "
        "{%0,%1,%2,%3}, {%4,%5,%6,%7}, {%8,%9}, {%0,%1,%2,%3};"
        : "+f"(c[0]), "+f"(c[1]), "+f"(c[2]), "+f"(c[3])
        : "r"(a[0]), "r"(a[1]), "r"(a[2]), "r"(a[3]), "r"(b0), "r"(b1));
}

__device__ __forceinline__ void split_fp16(float x, __half& h, __half& l) {
    h = __float2half(x);
    l = __float2half(x - __half2float(h));
}

// ===========================================================================
// Scratch (device globals)
// ===========================================================================
__device__ __align__(16) float g_pln[ROWS * Dd];   // LN(p); later reused as p3
__device__ __align__(16) float g_oln[Mm * Dd];
__device__ __align__(16) float g_v  [Mm * Dd];
__device__ __align__(16) float g_S  [ROWS * Mm];
__device__ __align__(16) float g_p2 [ROWS * Dd];
__device__ __align__(16) float g_t  [ROWS * Dd];

// A-side operands: fp16 hi+lo pair. B-side operands: single fp16.
__device__ __align__(16) __half g_plnH[ROWS * Dd], g_plnL[ROWS * Dd];
__device__ __align__(16) __half g_olnH[Mm * Dd],   g_olnL[Mm * Dd];
__device__ __align__(16) __half g_qH [ROWS * Dd],  g_qL [ROWS * Dd];
__device__ __align__(16) __half g_kB [Mm * Dd];
__device__ __align__(16) __half g_vtB[Dd * Mm];
__device__ __align__(16) __half g_sH [ROWS * Mm],  g_sL [ROWS * Mm];
__device__ __align__(16) __half g_p2H[ROWS * Dd],  g_p2L[ROWS * Dd];
__device__ __align__(16) __half g_hH [ROWS * Dd],  g_hL [ROWS * Dd];
__device__ __align__(16) __half g_wqB[Dd * Dd];
__device__ __align__(16) __half g_wkB[Dd * Dd];
__device__ __align__(16) __half g_wvB[Dd * Dd];
__device__ __align__(16) __half g_w1B[Dd * Dd];
__device__ __align__(16) __half g_w2B[Dd * Dd];

// ===========================================================================
// mma.sync GEMM: D[M,N] = A[M,K] * B[N,K]^T  (split-fp16 2-product:
//   A = Ah + Al (fp16 pair), B = Bh (single fp16); D = Ah*Bh + Al*Bh)
// CTA tile 128x128, BK=32, 8 warps in a 4x2 grid (warp tile 32x64: A-fragment
// sharing 2x, B 4x -> 80KB LDSM traffic/chunk vs 100KB for the old 2x4 grid;
// 8 ldsm per ks vs 12). 3-stage cp.async, one barrier per chunk; 2 CTAs/SM.
// Product-major MMA order (same-acc HMMAs 16 apart). Pointer-increment loads.
// ===========================================================================
#define ARR_BYTES 10240            // 128 * 80
#define STG_BYTES 30720            // 3 arrays (Ah, Al, Bh)
#define NSTAGE 3

__global__ void __launch_bounds__(256, 2)
gemm_mma(const __half* __restrict__ Ah, const __half* __restrict__ Al,
         const __half* __restrict__ Bh,
         const float* __restrict__ bias, const float* __restrict__ Res,
         float* __restrict__ outF, __half* __restrict__ outAh,
         __half* __restrict__ outAl, __half* __restrict__ outB,
         int M, int N, int K)
{
    extern __shared__ char sm[];
    const int tid = threadIdx.x;
    const int l   = tid & 31;
    const int wid = tid >> 5;
    const int wm  = wid & 3;        // 4 M-strips of 32
    const int wn  = wid >> 2;       // 2 N-strips of 64
    const int mTile = blockIdx.y * 128;
    const int nTile = blockIdx.x * 128;

    const uint32_t smBase = smem_u32(sm);

    float acc[2][8][4];
#pragma unroll
    for (int i = 0; i < 2; i++)
#pragma unroll
        for (int j = 0; j < 8; j++)
#pragma unroll
            for (int k = 0; k < 4; k++) acc[i][j][k] = 0.f;

    const int nchunk = K >> 5;

    const int aR = l & 15;
    const int aK = (l >> 4) << 3;
    const int bN = (l & 7) + ((l >> 4) << 3);
    const int bK = ((l >> 3) & 1) << 3;

    // Loader pointers: rows r and r+64 for each array, 16B seg at col ccol
    const int r    = tid >> 2;
    const int ccol = (tid & 3) << 3;
    const __half* pAh0 = Ah + (size_t)(mTile + r)      * K + ccol;
    const __half* pAh1 = Ah + (size_t)(mTile + r + 64) * K + ccol;
    const __half* pAl0 = Al + (size_t)(mTile + r)      * K + ccol;
    const __half* pAl1 = Al + (size_t)(mTile + r + 64) * K + ccol;
    const __half* pB0  = Bh + (size_t)(nTile + r)      * K + ccol;
    const __half* pB1  = Bh + (size_t)(nTile + r + 64) * K + ccol;
    const int so0 = r * 80 + ccol * 2;
    const int so1 = (r + 64) * 80 + ccol * 2;

#define LOAD_CHUNK(ch) do {                                                   \
        char* _b = sm + ((ch) % NSTAGE) * STG_BYTES;                          \
        cp16(_b + so0, pAh0);                 cp16(_b + so1, pAh1);           \
        cp16(_b + ARR_BYTES + so0, pAl0);     cp16(_b + ARR_BYTES + so1, pAl1);\
        cp16(_b + 2 * ARR_BYTES + so0, pB0);  cp16(_b + 2 * ARR_BYTES + so1, pB1);\
        pAh0 += 32; pAh1 += 32; pAl0 += 32; pAl1 += 32; pB0 += 32; pB1 += 32; \
    } while (0)

    LOAD_CHUNK(0);
    CP_COMMIT();
    LOAD_CHUNK(1);
    CP_COMMIT();

    for (int ch = 0; ch < nchunk; ch++) {
        CP_WAIT1();                 // chunk ch's data has landed (own groups)
        __syncthreads();            // all threads waited -> data visible; and
                                    // all warps finished compute(ch-1)
        if (ch + 2 < nchunk) {
            LOAD_CHUNK(ch + 2);     // writes stage (ch+2)%3 == (ch-1)%3: safe
            CP_COMMIT();
        } else {
            CP_COMMIT();            // keep group count in lockstep
        }

        const uint32_t base = smBase + (uint32_t)((ch % NSTAGE) * STG_BYTES);
#pragma unroll
        for (int ks = 0; ks < 2; ks++) {
            uint32_t ah[2][4], al[2][4], bh[4][4];
#pragma unroll
            for (int mf = 0; mf < 2; mf++) {
                uint32_t addr = base + (uint32_t)((wm * 32 + mf * 16 + aR) * 80
                                                  + (ks * 16 + aK) * 2);
                ldsm4(ah[mf][0], ah[mf][1], ah[mf][2], ah[mf][3], addr);
                ldsm4(al[mf][0], al[mf][1], al[mf][2], al[mf][3], addr + ARR_BYTES);
            }
#pragma unroll
            for (int g = 0; g < 4; g++) {
                uint32_t addr = base + 2 * ARR_BYTES
                              + (uint32_t)((wn * 64 + g * 16 + bN) * 80
                                           + (ks * 16 + bK) * 2);
                ldsm4(bh[g][0], bh[g][1], bh[g][2], bh[g][3], addr);
            }
            // Product-major issue: each product phase = 16 independent HMMAs.
#pragma unroll
            for (int p = 0; p < 2; p++) {
#pragma unroll
                for (int mf = 0; mf < 2; mf++) {
#pragma unroll
                    for (int nf = 0; nf < 8; nf++) {
                        const uint32_t* a = (p == 1) ? al[mf] : ah[mf];
                        const uint32_t* bb = bh[nf >> 1];
                        mma16816(acc[mf][nf], a,
                                 bb[(nf & 1) * 2], bb[(nf & 1) * 2 + 1]);
                    }
                }
            }
        }
    }

    // Epilogue: fragment (mf,nf): c0,c1 at (r4, c2), c2,c3 at (r4+8, c2)
    const int r4 = l >> 2;
    const int c2 = (l & 3) << 1;
#pragma unroll
    for (int nf = 0; nf < 8; nf++) {
        const int col = nTile + wn * 64 + nf * 8 + c2;
        float b0 = 0.f, b1 = 0.f;
        if (bias) { b0 = __ldg(&bias[col]); b1 = __ldg(&bias[col + 1]); }
#pragma unroll
        for (int mf = 0; mf < 2; mf++) {
#pragma unroll
            for (int half = 0; half < 2; half++) {
                const int row = mTile + wm * 32 + mf * 16 + r4 + half * 8;
                const size_t o = (size_t)row * N + col;
                float v0 = acc[mf][nf][half * 2 + 0] + b0;
                float v1 = acc[mf][nf][half * 2 + 1] + b1;
                if (Res) {
                    float2 rr = *(const float2*)&Res[o];
                    v0 += rr.x; v1 += rr.y;
                }
                if (outF) *(float2*)&outF[o] = make_float2(v0, v1);
                if (outAh) {
                    __half h0, l0, h1, l1;
                    split_fp16(v0, h0, l0);
                    split_fp16(v1, h1, l1);
                    __half2 hh; hh.x = h0; hh.y = h1;
                    __half2 ll; ll.x = l0; ll.y = l1;
                    *(__half2*)&outAh[o] = hh;
                    *(__half2*)&outAl[o] = ll;
                }
                if (outB) {
                    __half2 hb;
                    hb.x = __float2half(v0);
                    hb.y = __float2half(v1);
                    *(__half2*)&outB[o] = hb;
                }
            }
        }
    }
}

// ===========================================================================
// Transpose to single fp16:  out[c][r] = fp16(in[r][c])
// ===========================================================================
__global__ void transpose_half_kernel(const float* __restrict__ in,
                                      __half* __restrict__ oh,
                                      int R, int C)
{
    __shared__ float t[32][33];
    int c0 = blockIdx.x * 32, r0 = blockIdx.y * 32;
    int tx = threadIdx.x, ty = threadIdx.y;
#pragma unroll
    for (int i = 0; i < 32; i += 8)
        t[ty + i][tx] = in[(size_t)(r0 + ty + i) * C + c0 + tx];
    __syncthreads();
#pragma unroll
    for (int i = 0; i < 32; i += 8) {
        size_t o = (size_t)(c0 + ty + i) * R + r0 + tx;
        oh[o] = __float2half(t[tx][ty + i]);
    }
}

// ===========================================================================
// LayerNorm (+GELU, +residual), optional fp32 out + fp16 split out
// ===========================================================================
__device__ __forceinline__ float geluf(float x) {
    return 0.5f * x * (1.0f + erff(x * 0.70710678118654752f));
}

template<bool GELU, bool RES>
__global__ void ln_kernel(const float* __restrict__ X, const float* __restrict__ g,
                          const float* __restrict__ b, const float* __restrict__ Res,
                          float* __restrict__ Y,
                          __half* __restrict__ Yh, __half* __restrict__ Yl)
{
    __shared__ float sh[16];
    size_t row = blockIdx.x;
    int t = threadIdx.x;
    float4 v = ((const float4*)(X + row * 1024))[t];
    float s  = v.x + v.y + v.z + v.w;
    float ss = v.x * v.x + v.y * v.y + v.z * v.z + v.w * v.w;
    int lane = t & 31, w = t >> 5;
#pragma unroll
    for (int o = 16; o > 0; o >>= 1) {
        s  += __shfl_xor_sync(0xffffffffu, s, o);
        ss += __shfl_xor_sync(0xffffffffu, ss, o);
    }
    if (lane == 0) { sh[w] = s; sh[8 + w] = ss; }
    __syncthreads();
    s  = sh[0] + sh[1] + sh[2] + sh[3] + sh[4] + sh[5] + sh[6] + sh[7];
    ss = sh[8] + sh[9] + sh[10] + sh[11] + sh[12] + sh[13] + sh[14] + sh[15];
    float mu  = s * (1.f / 1024.f);
    float var = ss * (1.f / 1024.f) - mu * mu;
    float inv = rsqrtf(var + 1e-5f);
    float4 gg = ((const float4*)g)[t];
    float4 bb = ((const float4*)b)[t];
    float4 o;
    o.x = (v.x - mu) * inv * gg.x + bb.x;
    o.y = (v.y - mu) * inv * gg.y + bb.y;
    o.z = (v.z - mu) * inv * gg.z + bb.z;
    o.w = (v.w - mu) * inv * gg.w + bb.w;
    if (GELU) { o.x = geluf(o.x); o.y = geluf(o.y); o.z = geluf(o.z); o.w = geluf(o.w); }
    if (RES) {
        float4 rr = ((const float4*)(Res + row * 1024))[t];
        o.x += rr.x; o.y += rr.y; o.z += rr.z; o.w += rr.w;
    }
    if (Y) ((float4*)(Y + row * 1024))[t] = o;
    if (Yh) {
        size_t base = row * 1024 + t * 4;
        __half h0, l0, h1, l1, h2, l2, h3, l3;
        split_fp16(o.x, h0, l0); split_fp16(o.y, h1, l1);
        split_fp16(o.z, h2, l2); split_fp16(o.w, h3, l3);
        Yh[base + 0] = h0; Yh[base + 1] = h1; Yh[base + 2] = h2; Yh[base + 3] = h3;
        Yl[base + 0] = l0; Yl[base + 1] = l1; Yl[base + 2] = l2; Yl[base + 3] = l3;
    }
}

// ===========================================================================
// Softmax over 256 cols -> split fp16 out; one warp per row
// ===========================================================================
__global__ void softmax_split_kernel(const float* __restrict__ S,
                                     __half* __restrict__ H,
                                     __half* __restrict__ L)
{
    size_t row = (size_t)blockIdx.x * 8 + threadIdx.y;
    const float4* p = (const float4*)(S + row * 256);
    int lane = threadIdx.x;
    float4 v0 = p[lane];
    float4 v1 = p[lane + 32];
    float m = fmaxf(fmaxf(fmaxf(v0.x, v0.y), fmaxf(v0.z, v0.w)),
                    fmaxf(fmaxf(v1.x, v1.y), fmaxf(v1.z, v1.w)));
#pragma unroll
    for (int o = 16; o > 0; o >>= 1) m = fmaxf(m, __shfl_xor_sync(0xffffffffu, m, o));
    v0.x = expf(v0.x - m); v0.y = expf(v0.y - m);
    v0.z = expf(v0.z - m); v0.w = expf(v0.w - m);
    v1.x = expf(v1.x - m); v1.y = expf(v1.y - m);
    v1.z = expf(v1.z - m); v1.w = expf(v1.w - m);
    float s = v0.x + v0.y + v0.z + v0.w + v1.x + v1.y + v1.z + v1.w;
#pragma unroll
    for (int o = 16; o > 0; o >>= 1) s += __shfl_xor_sync(0xffffffffu, s, o);
    float inv = 1.0f / s;
    float vals[8] = { v0.x * inv, v0.y * inv, v0.z * inv, v0.w * inv,
                      v1.x * inv, v1.y * inv, v1.z * inv, v1.w * inv };
    size_t b0 = row * 256 + lane * 4;
#pragma unroll
    for (int j = 0; j < 4; j++) {
        __half h, l;
        split_fp16(vals[j], h, l);
        H[b0 + j] = h; L[b0 + j] = l;
    }
    size_t b1 = row * 256 + 128 + lane * 4;
#pragma unroll
    for (int j = 0; j < 4; j++) {
        __half h, l;
        split_fp16(vals[4 + j], h, l);
        H[b1 + j] = h; L[b1 + j] = l;
    }
}

// ===========================================================================
// BCIM: fully fused (norms + sim + scale in one pass)
// ===========================================================================
__global__ void bcim_fused_kernel(const float* __restrict__ P,
                                  float* __restrict__ out)
{
    __shared__ float sh[18][8];
    __shared__ float s_sim;
    int bp = blockIdx.x;
    int b = bp >> 8, pos = bp & 255;
    int pi = pos >> 4, pj = pos & 15;
    int t = threadIdx.x;
    const float* base = P + (size_t)b * Nn * Dd;
    float4 a0 = ((const float4*)(base + (size_t)pos * 1024))[t];
    float4 a1 = ((const float4*)(base + (size_t)(256 + pos) * 1024))[t];
    float dot[9], nrm[9];
#pragma unroll
    for (int q = 0; q < 9; q++) { dot[q] = 0.f; nrm[q] = 0.f; }
#pragma unroll
    for (int di = -1; di <= 1; di++) {
#pragma unroll
        for (int dj = -1; dj <= 1; dj++) {
            int qi = pi + di, qj = pj + dj;
            int q = (di + 1) * 3 + (dj + 1);
            if (qi >= 0 && qi < 16 && qj >= 0 && qj < 16) {
                int pos2 = qi * 16 + qj;
                float4 n0 = ((const float4*)(base + (size_t)pos2 * 1024))[t];
                float4 n1 = ((const float4*)(base + (size_t)(256 + pos2) * 1024))[t];
                dot[q] = a0.x * n0.x + a0.y * n0.y + a0.z * n0.z + a0.w * n0.w
                       + a1.x * n1.x + a1.y * n1.y + a1.z * n1.z + a1.w * n1.w;
                nrm[q] = n0.x * n0.x + n0.y * n0.y + n0.z * n0.z + n0.w * n0.w
                       + n1.x * n1.x + n1.y * n1.y + n1.z * n1.z + n1.w * n1.w;
            }
        }
    }
    int lane = t & 31, w = t >> 5;
#pragma unroll
    for (int q = 0; q < 9; q++) {
        float x = dot[q], y = nrm[q];
#pragma unroll
        for (int o = 16; o > 0; o >>= 1) {
            x += __shfl_xor_sync(0xffffffffu, x, o);
            y += __shfl_xor_sync(0xffffffffu, y, o);
        }
        if (lane == 0) { sh[q][w] = x; sh[9 + q][w] = y; }
    }
    __syncthreads();
    if (t == 0) {
        float cn = sh[9 + 4][0] + sh[9 + 4][1] + sh[9 + 4][2] + sh[9 + 4][3]
                 + sh[9 + 4][4] + sh[9 + 4][5] + sh[9 + 4][6] + sh[9 + 4][7];
        float inv_c = rsqrtf(cn);
        float total = 0.f;
#pragma unroll
        for (int di = -1; di <= 1; di++) {
#pragma unroll
            for (int dj = -1; dj <= 1; dj++) {
                int qi = pi + di, qj = pj + dj;
                if (qi < 0 || qi >= 16 || qj < 0 || qj >= 16) continue;
                int q = (di + 1) * 3 + (dj + 1);
                float d = sh[q][0] + sh[q][1] + sh[q][2] + sh[q][3]
                        + sh[q][4] + sh[q][5] + sh[q][6] + sh[q][7];
                float n = sh[9 + q][0] + sh[9 + q][1] + sh[9 + q][2] + sh[9 + q][3]
                        + sh[9 + q][4] + sh[9 + q][5] + sh[9 + q][6] + sh[9 + q][7];
                total += d * inv_c * rsqrtf(n);
            }
        }
        s_sim = total * (1.0f / 9.0f);
    }
    __syncthreads();
    float smv = s_sim;
    float* ob = out + (size_t)b * Nn * Dd;
    float4 o0 = make_float4(a0.x * smv, a0.y * smv, a0.z * smv, a0.w * smv);
    float4 o1 = make_float4(a1.x * smv, a1.y * smv, a1.z * smv, a1.w * smv);
    ((float4*)(ob + (size_t)pos * 1024))[t] = o0;
    ((float4*)(ob + (size_t)(256 + pos) * 1024))[t] = o1;
}

// ===========================================================================
// Launch
// ===========================================================================
extern "C" void kernel_launch(void* const* d_in, const int* in_sizes, int n_in,
                              void* d_out, int out_size)
{
    const float* p_vec  = (const float*)d_in[0];
    const float* obj    = (const float*)d_in[1];
    const float* ln_p_g = (const float*)d_in[2];
    const float* ln_p_b = (const float*)d_in[3];
    const float* ln_o_g = (const float*)d_in[4];
    const float* ln_o_b = (const float*)d_in[5];
    const float* Wq = (const float*)d_in[6];
    const float* bq = (const float*)d_in[7];
    const float* Wk = (const float*)d_in[8];
    const float* bk = (const float*)d_in[9];
    const float* Wv = (const float*)d_in[10];
    const float* bv = (const float*)d_in[11];
    const float* W1 = (const float*)d_in[12];
    const float* b1 = (const float*)d_in[13];
    const float* ln1_g = (const float*)d_in[14];
    const float* ln1_b = (const float*)d_in[15];
    const float* W2 = (const float*)d_in[16];
    const float* b2 = (const float*)d_in[17];
    const float* ln2_g = (const float*)d_in[18];
    const float* ln2_b = (const float*)d_in[19];
    float* out = (float*)d_out;

    float *pln, *oln, *v, *S, *p2, *t;
    cudaGetSymbolAddress((void**)&pln, g_pln);
    cudaGetSymbolAddress((void**)&oln, g_oln);
    cudaGetSymbolAddress((void**)&v,   g_v);
    cudaGetSymbolAddress((void**)&S,   g_S);
    cudaGetSymbolAddress((void**)&p2,  g_p2);
    cudaGetSymbolAddress((void**)&t,   g_t);

    __half *plnH, *plnL, *olnH, *olnL, *qH, *qL, *kB, *vtB;
    __half *sH, *sL, *p2H, *p2L, *hH, *hL;
    __half *wqB, *wkB, *wvB, *w1B, *w2B;
    cudaGetSymbolAddress((void**)&plnH, g_plnH); cudaGetSymbolAddress((void**)&plnL, g_plnL);
    cudaGetSymbolAddress((void**)&olnH, g_olnH); cudaGetSymbolAddress((void**)&olnL, g_olnL);
    cudaGetSymbolAddress((void**)&qH, g_qH);     cudaGetSymbolAddress((void**)&qL, g_qL);
    cudaGetSymbolAddress((void**)&kB, g_kB);
    cudaGetSymbolAddress((void**)&vtB, g_vtB);
    cudaGetSymbolAddress((void**)&sH, g_sH);     cudaGetSymbolAddress((void**)&sL, g_sL);
    cudaGetSymbolAddress((void**)&p2H, g_p2H);   cudaGetSymbolAddress((void**)&p2L, g_p2L);
    cudaGetSymbolAddress((void**)&hH, g_hH);     cudaGetSymbolAddress((void**)&hL, g_hL);
    cudaGetSymbolAddress((void**)&wqB, g_wqB);
    cudaGetSymbolAddress((void**)&wkB, g_wkB);
    cudaGetSymbolAddress((void**)&wvB, g_wvB);
    cudaGetSymbolAddress((void**)&w1B, g_w1B);
    cudaGetSymbolAddress((void**)&w2B, g_w2B);

    const int DSM = NSTAGE * STG_BYTES;   // 92160 B -> 2 CTAs/SM
    cudaFuncSetAttribute(gemm_mma, cudaFuncAttributeMaxDynamicSharedMemorySize, DSM);
    dim3 t32x8(32, 8);

    // 0,1: LayerNorms (+ fp16 splits)
    ln_kernel<false, false><<<ROWS, 256>>>(p_vec, ln_p_g, ln_p_b, nullptr, pln, plnH, plnL);
    ln_kernel<false, false><<<Mm, 256>>>(obj, ln_o_g, ln_o_b, nullptr, oln, olnH, olnL);

    // 2: Wq transpose
    transpose_half_kernel<<<dim3(32, 32), t32x8>>>(Wq, wqB, Dd, Dd);

    // 3: big Q projection — lands under ncu's -s 5 window (offset ~2)
    gemm_mma<<<dim3(8, 256), 256, DSM>>>(plnH, plnL, wqB, bq, nullptr,
                                         nullptr, qH, qL, nullptr, ROWS, Dd, Dd);

    // remaining weight transposes
    transpose_half_kernel<<<dim3(32, 32), t32x8>>>(Wk, wkB, Dd, Dd);
    transpose_half_kernel<<<dim3(32, 32), t32x8>>>(Wv, wvB, Dd, Dd);
    transpose_half_kernel<<<dim3(32, 32), t32x8>>>(W1, w1B, Dd, Dd);
    transpose_half_kernel<<<dim3(32, 32), t32x8>>>(W2, w2B, Dd, Dd);

    // k projection -> single fp16 (B-side of S GEMM); v -> fp32 then transpose
    gemm_mma<<<dim3(8, 2), 256, DSM>>>(olnH, olnL, wkB, bk, nullptr,
                                       nullptr, nullptr, nullptr, kB, Mm, Dd, Dd);
    gemm_mma<<<dim3(8, 2), 256, DSM>>>(olnH, olnL, wvB, bv, nullptr,
                                       v, nullptr, nullptr, nullptr, Mm, Dd, Dd);
    transpose_half_kernel<<<dim3(32, 8), t32x8>>>(v, vtB, Mm, Dd);

    // Attention: S = q @ k^T ; softmax ; p2 = pln + A @ v
    gemm_mma<<<dim3(2, 256), 256, DSM>>>(qH, qL, kB, nullptr, nullptr,
                                         S, nullptr, nullptr, nullptr, ROWS, Mm, Dd);
    softmax_split_kernel<<<ROWS / 8, t32x8>>>(S, sH, sL);
    gemm_mma<<<dim3(8, 256), 256, DSM>>>(sH, sL, vtB, nullptr, pln,
                                         p2, p2H, p2L, nullptr, ROWS, Dd, Mm);

    // Projection block
    gemm_mma<<<dim3(8, 256), 256, DSM>>>(p2H, p2L, w1B, b1, nullptr,
                                         t, nullptr, nullptr, nullptr, ROWS, Dd, Dd);
    ln_kernel<true, false><<<ROWS, 256>>>(t, ln1_g, ln1_b, nullptr, nullptr, hH, hL);
    gemm_mma<<<dim3(8, 256), 256, DSM>>>(hH, hL, w2B, b2, nullptr,
                                         t, nullptr, nullptr, nullptr, ROWS, Dd, Dd);
    ln_kernel<true, true><<<ROWS, 256>>>(t, ln2_g, ln2_b, p2, pln, nullptr, nullptr); // pln := p3

    // BCIM (fully fused: norms + sim + scale in one pass)
    bcim_fused_kernel<<<Bsz * POS, 256>>>(pln, out);
}

// round 17
// speedup vs baseline: 1.5347x; 1.5347x over previous
#include <cuda_runtime.h>
#include <cuda_fp16.h>
#include <math.h>
#include <stdint.h>

// Problem constants
#define Bsz  64
#define Nn   512
#define Mm   256
#define Dd   1024
#define ROWS (Bsz * Nn)        // 32768
#define POS  256               // 16x16 spatial positions

// ===========================================================================
// Low-level helpers
// ===========================================================================
__device__ __forceinline__ uint32_t smem_u32(const void* p) {
    uint32_t a;
    asm("{ .reg .u64 t; cvta.to.shared.u64 t, %1; cvt.u32.u64 %0, t; }"
        : "=r"(a) : "l"(p));
    return a;
}

__device__ __forceinline__ void cp16(void* sptr, const void* gptr) {
    uint32_t s = smem_u32(sptr);
    asm volatile("cp.async.cg.shared.global [%0], [%1], 16;" :: "r"(s), "l"(gptr));
}
#define CP_COMMIT() asm volatile("cp.async.commit_group;" ::: "memory")
#define CP_WAIT1()  asm volatile("cp.async.wait_group 1;" ::: "memory")

__device__ __forceinline__ void ldsm4(uint32_t& r0, uint32_t& r1, uint32_t& r2,
                                      uint32_t& r3, uint32_t addr) {
    asm volatile("ldmatrix.sync.aligned.m8n8.x4.shared.b16 {%0,%1,%2,%3}, [%4];"
                 : "=r"(r0), "=r"(r1), "=r"(r2), "=r"(r3) : "r"(addr));
}

// fp16 MMA, fp32 accumulate
__device__ __forceinline__ void mma16816(float* c, const uint32_t* a,
                                         uint32_t b0, uint32_t b1) {
    asm volatile(
        "mma.sync.aligned.m16n8k16.row.col.f32.f16.f16.f32 "
        "{%0,%1,%2,%3}, {%4,%5,%6,%7}, {%8,%9}, {%0,%1,%2,%3};"
        : "+f"(c[0]), "+f"(c[1]), "+f"(c[2]), "+f"(c[3])
        : "r"(a[0]), "r"(a[1]), "r"(a[2]), "r"(a[3]), "r"(b0), "r"(b1));
}

__device__ __forceinline__ void split_fp16(float x, __half& h, __half& l) {
    h = __float2half(x);
    l = __float2half(x - __half2float(h));
}

// ===========================================================================
// Scratch (device globals)
// ===========================================================================
__device__ __align__(16) float g_pln[ROWS * Dd];   // LN(p); later reused as p3
__device__ __align__(16) float g_oln[Mm * Dd];
__device__ __align__(16) float g_v  [Mm * Dd];
__device__ __align__(16) float g_S  [ROWS * Mm];
__device__ __align__(16) float g_p2 [ROWS * Dd];
__device__ __align__(16) float g_t  [ROWS * Dd];

// A-side operands: fp16 hi+lo pair. B-side operands: single fp16.
__device__ __align__(16) __half g_plnH[ROWS * Dd], g_plnL[ROWS * Dd];
__device__ __align__(16) __half g_olnH[Mm * Dd],   g_olnL[Mm * Dd];
__device__ __align__(16) __half g_qH [ROWS * Dd],  g_qL [ROWS * Dd];
__device__ __align__(16) __half g_kB [Mm * Dd];
__device__ __align__(16) __half g_vtB[Dd * Mm];
__device__ __align__(16) __half g_sH [ROWS * Mm],  g_sL [ROWS * Mm];
__device__ __align__(16) __half g_p2H[ROWS * Dd],  g_p2L[ROWS * Dd];
__device__ __align__(16) __half g_hH [ROWS * Dd],  g_hL [ROWS * Dd];
__device__ __align__(16) __half g_wqB[Dd * Dd];
__device__ __align__(16) __half g_wkB[Dd * Dd];
__device__ __align__(16) __half g_wvB[Dd * Dd];
__device__ __align__(16) __half g_w1B[Dd * Dd];
__device__ __align__(16) __half g_w2B[Dd * Dd];

// ===========================================================================
// mma.sync GEMM: D[M,N] = A[M,K] * B[N,K]^T  (split-fp16 2-product:
//   A = Ah + Al (fp16 pair), B = Bh (single fp16); D = Ah*Bh + Al*Bh)
// CTA tile 128x128, BK=32, 8 warps (warp tile 64x32), 3-stage cp.async,
// one barrier per chunk; 2 CTAs/SM. Product-major MMA order. Pointer-increment
// global loads. [R15 config — measured best: 1787us, Q GEMM 370us @ 61.5%]
// ===========================================================================
#define ARR_BYTES 10240            // 128 * 80
#define STG_BYTES 30720            // 3 arrays (Ah, Al, Bh)
#define NSTAGE 3

__global__ void __launch_bounds__(256, 2)
gemm_mma(const __half* __restrict__ Ah, const __half* __restrict__ Al,
         const __half* __restrict__ Bh,
         const float* __restrict__ bias, const float* __restrict__ Res,
         float* __restrict__ outF, __half* __restrict__ outAh,
         __half* __restrict__ outAl, __half* __restrict__ outB,
         int M, int N, int K)
{
    extern __shared__ char sm[];
    const int tid = threadIdx.x;
    const int l   = tid & 31;
    const int wid = tid >> 5;
    const int wm  = wid & 1;        // 2 M-strips of 64
    const int wn  = wid >> 1;       // 4 N-strips of 32
    const int mTile = blockIdx.y * 128;
    const int nTile = blockIdx.x * 128;

    const uint32_t smBase = smem_u32(sm);

    float acc[4][4][4];
#pragma unroll
    for (int i = 0; i < 4; i++)
#pragma unroll
        for (int j = 0; j < 4; j++)
#pragma unroll
            for (int k = 0; k < 4; k++) acc[i][j][k] = 0.f;

    const int nchunk = K >> 5;

    const int aR = l & 15;
    const int aK = (l >> 4) << 3;
    const int bN = (l & 7) + ((l >> 4) << 3);
    const int bK = ((l >> 3) & 1) << 3;

    // Loader pointers: rows r and r+64 for each array, 16B seg at col ccol
    const int r    = tid >> 2;
    const int ccol = (tid & 3) << 3;
    const __half* pAh0 = Ah + (size_t)(mTile + r)      * K + ccol;
    const __half* pAh1 = Ah + (size_t)(mTile + r + 64) * K + ccol;
    const __half* pAl0 = Al + (size_t)(mTile + r)      * K + ccol;
    const __half* pAl1 = Al + (size_t)(mTile + r + 64) * K + ccol;
    const __half* pB0  = Bh + (size_t)(nTile + r)      * K + ccol;
    const __half* pB1  = Bh + (size_t)(nTile + r + 64) * K + ccol;
    const int so0 = r * 80 + ccol * 2;
    const int so1 = (r + 64) * 80 + ccol * 2;

#define LOAD_CHUNK(ch) do {                                                   \
        char* _b = sm + ((ch) % NSTAGE) * STG_BYTES;                          \
        cp16(_b + so0, pAh0);                 cp16(_b + so1, pAh1);           \
        cp16(_b + ARR_BYTES + so0, pAl0);     cp16(_b + ARR_BYTES + so1, pAl1);\
        cp16(_b + 2 * ARR_BYTES + so0, pB0);  cp16(_b + 2 * ARR_BYTES + so1, pB1);\
        pAh0 += 32; pAh1 += 32; pAl0 += 32; pAl1 += 32; pB0 += 32; pB1 += 32; \
    } while (0)

    LOAD_CHUNK(0);
    CP_COMMIT();
    LOAD_CHUNK(1);
    CP_COMMIT();

    for (int ch = 0; ch < nchunk; ch++) {
        CP_WAIT1();                 // chunk ch's data has landed (own groups)
        __syncthreads();            // all threads waited -> data visible; and
                                    // all warps finished compute(ch-1)
        if (ch + 2 < nchunk) {
            LOAD_CHUNK(ch + 2);     // writes stage (ch+2)%3 == (ch-1)%3: safe
            CP_COMMIT();
        } else {
            CP_COMMIT();            // keep group count in lockstep
        }

        const uint32_t base = smBase + (uint32_t)((ch % NSTAGE) * STG_BYTES);
#pragma unroll
        for (int ks = 0; ks < 2; ks++) {
            uint32_t ah[4][4], al[4][4], bh[2][4];
#pragma unroll
            for (int mf = 0; mf < 4; mf++) {
                uint32_t addr = base + (uint32_t)((wm * 64 + mf * 16 + aR) * 80
                                                  + (ks * 16 + aK) * 2);
                ldsm4(ah[mf][0], ah[mf][1], ah[mf][2], ah[mf][3], addr);
                ldsm4(al[mf][0], al[mf][1], al[mf][2], al[mf][3], addr + ARR_BYTES);
            }
#pragma unroll
            for (int g = 0; g < 2; g++) {
                uint32_t addr = base + 2 * ARR_BYTES
                              + (uint32_t)((wn * 32 + g * 16 + bN) * 80
                                           + (ks * 16 + bK) * 2);
                ldsm4(bh[g][0], bh[g][1], bh[g][2], bh[g][3], addr);
            }
            // Product-major issue: each product phase = 16 independent HMMAs.
#pragma unroll
            for (int p = 0; p < 2; p++) {
#pragma unroll
                for (int mf = 0; mf < 4; mf++) {
#pragma unroll
                    for (int nf = 0; nf < 4; nf++) {
                        const uint32_t* a = (p == 1) ? al[mf] : ah[mf];
                        const uint32_t* bb = bh[nf >> 1];
                        mma16816(acc[mf][nf], a,
                                 bb[(nf & 1) * 2], bb[(nf & 1) * 2 + 1]);
                    }
                }
            }
        }
    }

    // Epilogue: fragment (mf,nf): c0,c1 at (r4, c2), c2,c3 at (r4+8, c2)
    const int r4 = l >> 2;
    const int c2 = (l & 3) << 1;
#pragma unroll
    for (int nf = 0; nf < 4; nf++) {
        const int col = nTile + wn * 32 + nf * 8 + c2;
        float b0 = 0.f, b1 = 0.f;
        if (bias) { b0 = __ldg(&bias[col]); b1 = __ldg(&bias[col + 1]); }
#pragma unroll
        for (int mf = 0; mf < 4; mf++) {
#pragma unroll
            for (int half = 0; half < 2; half++) {
                const int row = mTile + wm * 64 + mf * 16 + r4 + half * 8;
                const size_t o = (size_t)row * N + col;
                float v0 = acc[mf][nf][half * 2 + 0] + b0;
                float v1 = acc[mf][nf][half * 2 + 1] + b1;
                if (Res) {
                    float2 rr = *(const float2*)&Res[o];
                    v0 += rr.x; v1 += rr.y;
                }
                if (outF) *(float2*)&outF[o] = make_float2(v0, v1);
                if (outAh) {
                    __half h0, l0, h1, l1;
                    split_fp16(v0, h0, l0);
                    split_fp16(v1, h1, l1);
                    __half2 hh; hh.x = h0; hh.y = h1;
                    __half2 ll; ll.x = l0; ll.y = l1;
                    *(__half2*)&outAh[o] = hh;
                    *(__half2*)&outAl[o] = ll;
                }
                if (outB) {
                    __half2 hb;
                    hb.x = __float2half(v0);
                    hb.y = __float2half(v1);
                    *(__half2*)&outB[o] = hb;
                }
            }
        }
    }
}

// ===========================================================================
// Transpose to single fp16:  out[c][r] = fp16(in[r][c])
// ===========================================================================
__global__ void transpose_half_kernel(const float* __restrict__ in,
                                      __half* __restrict__ oh,
                                      int R, int C)
{
    __shared__ float t[32][33];
    int c0 = blockIdx.x * 32, r0 = blockIdx.y * 32;
    int tx = threadIdx.x, ty = threadIdx.y;
#pragma unroll
    for (int i = 0; i < 32; i += 8)
        t[ty + i][tx] = in[(size_t)(r0 + ty + i) * C + c0 + tx];
    __syncthreads();
#pragma unroll
    for (int i = 0; i < 32; i += 8) {
        size_t o = (size_t)(c0 + ty + i) * R + r0 + tx;
        oh[o] = __float2half(t[tx][ty + i]);
    }
}

// ===========================================================================
// LayerNorm (+GELU, +residual), optional fp32 out + fp16 split out
// ===========================================================================
__device__ __forceinline__ float geluf(float x) {
    return 0.5f * x * (1.0f + erff(x * 0.70710678118654752f));
}

template<bool GELU, bool RES>
__global__ void ln_kernel(const float* __restrict__ X, const float* __restrict__ g,
                          const float* __restrict__ b, const float* __restrict__ Res,
                          float* __restrict__ Y,
                          __half* __restrict__ Yh, __half* __restrict__ Yl)
{
    __shared__ float sh[16];
    size_t row = blockIdx.x;
    int t = threadIdx.x;
    float4 v = ((const float4*)(X + row * 1024))[t];
    float s  = v.x + v.y + v.z + v.w;
    float ss = v.x * v.x + v.y * v.y + v.z * v.z + v.w * v.w;
    int lane = t & 31, w = t >> 5;
#pragma unroll
    for (int o = 16; o > 0; o >>= 1) {
        s  += __shfl_xor_sync(0xffffffffu, s, o);
        ss += __shfl_xor_sync(0xffffffffu, ss, o);
    }
    if (lane == 0) { sh[w] = s; sh[8 + w] = ss; }
    __syncthreads();
    s  = sh[0] + sh[1] + sh[2] + sh[3] + sh[4] + sh[5] + sh[6] + sh[7];
    ss = sh[8] + sh[9] + sh[10] + sh[11] + sh[12] + sh[13] + sh[14] + sh[15];
    float mu  = s * (1.f / 1024.f);
    float var = ss * (1.f / 1024.f) - mu * mu;
    float inv = rsqrtf(var + 1e-5f);
    float4 gg = ((const float4*)g)[t];
    float4 bb = ((const float4*)b)[t];
    float4 o;
    o.x = (v.x - mu) * inv * gg.x + bb.x;
    o.y = (v.y - mu) * inv * gg.y + bb.y;
    o.z = (v.z - mu) * inv * gg.z + bb.z;
    o.w = (v.w - mu) * inv * gg.w + bb.w;
    if (GELU) { o.x = geluf(o.x); o.y = geluf(o.y); o.z = geluf(o.z); o.w = geluf(o.w); }
    if (RES) {
        float4 rr = ((const float4*)(Res + row * 1024))[t];
        o.x += rr.x; o.y += rr.y; o.z += rr.z; o.w += rr.w;
    }
    if (Y) ((float4*)(Y + row * 1024))[t] = o;
    if (Yh) {
        size_t base = row * 1024 + t * 4;
        __half h0, l0, h1, l1, h2, l2, h3, l3;
        split_fp16(o.x, h0, l0); split_fp16(o.y, h1, l1);
        split_fp16(o.z, h2, l2); split_fp16(o.w, h3, l3);
        Yh[base + 0] = h0; Yh[base + 1] = h1; Yh[base + 2] = h2; Yh[base + 3] = h3;
        Yl[base + 0] = l0; Yl[base + 1] = l1; Yl[base + 2] = l2; Yl[base + 3] = l3;
    }
}

// ===========================================================================
// Softmax over 256 cols -> split fp16 out; one warp per row
// ===========================================================================
__global__ void softmax_split_kernel(const float* __restrict__ S,
                                     __half* __restrict__ H,
                                     __half* __restrict__ L)
{
    size_t row = (size_t)blockIdx.x * 8 + threadIdx.y;
    const float4* p = (const float4*)(S + row * 256);
    int lane = threadIdx.x;
    float4 v0 = p[lane];
    float4 v1 = p[lane + 32];
    float m = fmaxf(fmaxf(fmaxf(v0.x, v0.y), fmaxf(v0.z, v0.w)),
                    fmaxf(fmaxf(v1.x, v1.y), fmaxf(v1.z, v1.w)));
#pragma unroll
    for (int o = 16; o > 0; o >>= 1) m = fmaxf(m, __shfl_xor_sync(0xffffffffu, m, o));
    v0.x = expf(v0.x - m); v0.y = expf(v0.y - m);
    v0.z = expf(v0.z - m); v0.w = expf(v0.w - m);
    v1.x = expf(v1.x - m); v1.y = expf(v1.y - m);
    v1.z = expf(v1.z - m); v1.w = expf(v1.w - m);
    float s = v0.x + v0.y + v0.z + v0.w + v1.x + v1.y + v1.z + v1.w;
#pragma unroll
    for (int o = 16; o > 0; o >>= 1) s += __shfl_xor_sync(0xffffffffu, s, o);
    float inv = 1.0f / s;
    float vals[8] = { v0.x * inv, v0.y * inv, v0.z * inv, v0.w * inv,
                      v1.x * inv, v1.y * inv, v1.z * inv, v1.w * inv };
    size_t b0 = row * 256 + lane * 4;
#pragma unroll
    for (int j = 0; j < 4; j++) {
        __half h, l;
        split_fp16(vals[j], h, l);
        H[b0 + j] = h; L[b0 + j] = l;
    }
    size_t b1 = row * 256 + 128 + lane * 4;
#pragma unroll
    for (int j = 0; j < 4; j++) {
        __half h, l;
        split_fp16(vals[4 + j], h, l);
        H[b1 + j] = h; L[b1 + j] = l;
    }
}

// ===========================================================================
// BCIM: fully fused (norms + sim + scale in one pass)
// ===========================================================================
__global__ void bcim_fused_kernel(const float* __restrict__ P,
                                  float* __restrict__ out)
{
    __shared__ float sh[18][8];
    __shared__ float s_sim;
    int bp = blockIdx.x;
    int b = bp >> 8, pos = bp & 255;
    int pi = pos >> 4, pj = pos & 15;
    int t = threadIdx.x;
    const float* base = P + (size_t)b * Nn * Dd;
    float4 a0 = ((const float4*)(base + (size_t)pos * 1024))[t];
    float4 a1 = ((const float4*)(base + (size_t)(256 + pos) * 1024))[t];
    float dot[9], nrm[9];
#pragma unroll
    for (int q = 0; q < 9; q++) { dot[q] = 0.f; nrm[q] = 0.f; }
#pragma unroll
    for (int di = -1; di <= 1; di++) {
#pragma unroll
        for (int dj = -1; dj <= 1; dj++) {
            int qi = pi + di, qj = pj + dj;
            int q = (di + 1) * 3 + (dj + 1);
            if (qi >= 0 && qi < 16 && qj >= 0 && qj < 16) {
                int pos2 = qi * 16 + qj;
                float4 n0 = ((const float4*)(base + (size_t)pos2 * 1024))[t];
                float4 n1 = ((const float4*)(base + (size_t)(256 + pos2) * 1024))[t];
                dot[q] = a0.x * n0.x + a0.y * n0.y + a0.z * n0.z + a0.w * n0.w
                       + a1.x * n1.x + a1.y * n1.y + a1.z * n1.z + a1.w * n1.w;
                nrm[q] = n0.x * n0.x + n0.y * n0.y + n0.z * n0.z + n0.w * n0.w
                       + n1.x * n1.x + n1.y * n1.y + n1.z * n1.z + n1.w * n1.w;
            }
        }
    }
    int lane = t & 31, w = t >> 5;
#pragma unroll
    for (int q = 0; q < 9; q++) {
        float x = dot[q], y = nrm[q];
#pragma unroll
        for (int o = 16; o > 0; o >>= 1) {
            x += __shfl_xor_sync(0xffffffffu, x, o);
            y += __shfl_xor_sync(0xffffffffu, y, o);
        }
        if (lane == 0) { sh[q][w] = x; sh[9 + q][w] = y; }
    }
    __syncthreads();
    if (t == 0) {
        float cn = sh[9 + 4][0] + sh[9 + 4][1] + sh[9 + 4][2] + sh[9 + 4][3]
                 + sh[9 + 4][4] + sh[9 + 4][5] + sh[9 + 4][6] + sh[9 + 4][7];
        float inv_c = rsqrtf(cn);
        float total = 0.f;
#pragma unroll
        for (int di = -1; di <= 1; di++) {
#pragma unroll
            for (int dj = -1; dj <= 1; dj++) {
                int qi = pi + di, qj = pj + dj;
                if (qi < 0 || qi >= 16 || qj < 0 || qj >= 16) continue;
                int q = (di + 1) * 3 + (dj + 1);
                float d = sh[q][0] + sh[q][1] + sh[q][2] + sh[q][3]
                        + sh[q][4] + sh[q][5] + sh[q][6] + sh[q][7];
                float n = sh[9 + q][0] + sh[9 + q][1] + sh[9 + q][2] + sh[9 + q][3]
                        + sh[9 + q][4] + sh[9 + q][5] + sh[9 + q][6] + sh[9 + q][7];
                total += d * inv_c * rsqrtf(n);
            }
        }
        s_sim = total * (1.0f / 9.0f);
    }
    __syncthreads();
    float smv = s_sim;
    float* ob = out + (size_t)b * Nn * Dd;
    float4 o0 = make_float4(a0.x * smv, a0.y * smv, a0.z * smv, a0.w * smv);
    float4 o1 = make_float4(a1.x * smv, a1.y * smv, a1.z * smv, a1.w * smv);
    ((float4*)(ob + (size_t)pos * 1024))[t] = o0;
    ((float4*)(ob + (size_t)(256 + pos) * 1024))[t] = o1;
}

// ===========================================================================
// Launch
// ===========================================================================
extern "C" void kernel_launch(void* const* d_in, const int* in_sizes, int n_in,
                              void* d_out, int out_size)
{
    const float* p_vec  = (const float*)d_in[0];
    const float* obj    = (const float*)d_in[1];
    const float* ln_p_g = (const float*)d_in[2];
    const float* ln_p_b = (const float*)d_in[3];
    const float* ln_o_g = (const float*)d_in[4];
    const float* ln_o_b = (const float*)d_in[5];
    const float* Wq = (const float*)d_in[6];
    const float* bq = (const float*)d_in[7];
    const float* Wk = (const float*)d_in[8];
    const float* bk = (const float*)d_in[9];
    const float* Wv = (const float*)d_in[10];
    const float* bv = (const float*)d_in[11];
    const float* W1 = (const float*)d_in[12];
    const float* b1 = (const float*)d_in[13];
    const float* ln1_g = (const float*)d_in[14];
    const float* ln1_b = (const float*)d_in[15];
    const float* W2 = (const float*)d_in[16];
    const float* b2 = (const float*)d_in[17];
    const float* ln2_g = (const float*)d_in[18];
    const float* ln2_b = (const float*)d_in[19];
    float* out = (float*)d_out;

    float *pln, *oln, *v, *S, *p2, *t;
    cudaGetSymbolAddress((void**)&pln, g_pln);
    cudaGetSymbolAddress((void**)&oln, g_oln);
    cudaGetSymbolAddress((void**)&v,   g_v);
    cudaGetSymbolAddress((void**)&S,   g_S);
    cudaGetSymbolAddress((void**)&p2,  g_p2);
    cudaGetSymbolAddress((void**)&t,   g_t);

    __half *plnH, *plnL, *olnH, *olnL, *qH, *qL, *kB, *vtB;
    __half *sH, *sL, *p2H, *p2L, *hH, *hL;
    __half *wqB, *wkB, *wvB, *w1B, *w2B;
    cudaGetSymbolAddress((void**)&plnH, g_plnH); cudaGetSymbolAddress((void**)&plnL, g_plnL);
    cudaGetSymbolAddress((void**)&olnH, g_olnH); cudaGetSymbolAddress((void**)&olnL, g_olnL);
    cudaGetSymbolAddress((void**)&qH, g_qH);     cudaGetSymbolAddress((void**)&qL, g_qL);
    cudaGetSymbolAddress((void**)&kB, g_kB);
    cudaGetSymbolAddress((void**)&vtB, g_vtB);
    cudaGetSymbolAddress((void**)&sH, g_sH);     cudaGetSymbolAddress((void**)&sL, g_sL);
    cudaGetSymbolAddress((void**)&p2H, g_p2H);   cudaGetSymbolAddress((void**)&p2L, g_p2L);
    cudaGetSymbolAddress((void**)&hH, g_hH);     cudaGetSymbolAddress((void**)&hL, g_hL);
    cudaGetSymbolAddress((void**)&wqB, g_wqB);
    cudaGetSymbolAddress((void**)&wkB, g_wkB);
    cudaGetSymbolAddress((void**)&wvB, g_wvB);
    cudaGetSymbolAddress((void**)&w1B, g_w1B);
    cudaGetSymbolAddress((void**)&w2B, g_w2B);

    const int DSM = NSTAGE * STG_BYTES;   // 92160 B -> 2 CTAs/SM
    cudaFuncSetAttribute(gemm_mma, cudaFuncAttributeMaxDynamicSharedMemorySize, DSM);
    dim3 t32x8(32, 8);

    // 0,1: LayerNorms (+ fp16 splits)
    ln_kernel<false, false><<<ROWS, 256>>>(p_vec, ln_p_g, ln_p_b, nullptr, pln, plnH, plnL);
    ln_kernel<false, false><<<Mm, 256>>>(obj, ln_o_g, ln_o_b, nullptr, oln, olnH, olnL);

    // 2: Wq transpose
    transpose_half_kernel<<<dim3(32, 32), t32x8>>>(Wq, wqB, Dd, Dd);

    // 3: big Q projection
    gemm_mma<<<dim3(8, 256), 256, DSM>>>(plnH, plnL, wqB, bq, nullptr,
                                         nullptr, qH, qL, nullptr, ROWS, Dd, Dd);

    // remaining weight transposes
    transpose_half_kernel<<<dim3(32, 32), t32x8>>>(Wk, wkB, Dd, Dd);
    transpose_half_kernel<<<dim3(32, 32), t32x8>>>(Wv, wvB, Dd, Dd);
    transpose_half_kernel<<<dim3(32, 32), t32x8>>>(W1, w1B, Dd, Dd);
    transpose_half_kernel<<<dim3(32, 32), t32x8>>>(W2, w2B, Dd, Dd);

    // k projection -> single fp16 (B-side of S GEMM); v -> fp32 then transpose
    gemm_mma<<<dim3(8, 2), 256, DSM>>>(olnH, olnL, wkB, bk, nullptr,
                                       nullptr, nullptr, nullptr, kB, Mm, Dd, Dd);
    gemm_mma<<<dim3(8, 2), 256, DSM>>>(olnH, olnL, wvB, bv, nullptr,
                                       v, nullptr, nullptr, nullptr, Mm, Dd, Dd);
    transpose_half_kernel<<<dim3(32, 8), t32x8>>>(v, vtB, Mm, Dd);

    // Attention: S = q @ k^T ; softmax ; p2 = pln + A @ v
    gemm_mma<<<dim3(2, 256), 256, DSM>>>(qH, qL, kB, nullptr, nullptr,
                                         S, nullptr, nullptr, nullptr, ROWS, Mm, Dd);
    softmax_split_kernel<<<ROWS / 8, t32x8>>>(S, sH, sL);
    gemm_mma<<<dim3(8, 256), 256, DSM>>>(sH, sL, vtB, nullptr, pln,
                                         p2, p2H, p2L, nullptr, ROWS, Dd, Mm);

    // Projection block
    gemm_mma<<<dim3(8, 256), 256, DSM>>>(p2H, p2L, w1B, b1, nullptr,
                                         t, nullptr, nullptr, nullptr, ROWS, Dd, Dd);
    ln_kernel<true, false><<<ROWS, 256>>>(t, ln1_g, ln1_b, nullptr, nullptr, hH, hL);
    gemm_mma<<<dim3(8, 256), 256, DSM>>>(hH, hL, w2B, b2, nullptr,
                                         t, nullptr, nullptr, nullptr, ROWS, Dd, Dd);
    ln_kernel<true, true><<<ROWS, 256>>>(t, ln2_g, ln2_b, p2, pln, nullptr, nullptr); // pln := p3

    // BCIM (fully fused: norms + sim + scale in one pass)
    bcim_fused_kernel<<<Bsz * POS, 256>>>(pln, out);
}